// round 1
// baseline (speedup 1.0000x reference)
#include <cuda_runtime.h>

// ContrastSSIMLoss: mean over |contrast(orig) - contrast(sim)|
// contrast(img)[b,y,x,s] = sum_c |img[b,c,y+w,x+w] - img[b,c,y+w+i,x+w+j]|
// shifts (i,j) in [-5,5]^2 excluding (0,0) -> 120 maps; region 246x246; B=16, C=3, H=256, w=5.

#define HDIM 256
#define WIN  5
#define RDIM 246              // HDIM - 2*WIN
#define BATCH 16
#define NCH 3

#define TX 64                 // output pixels per block in x
#define TY 8                  // output rows per block
#define PX 2                  // pixels per thread in x
#define BDX 32
#define BDY 8
#define SW (TX + 2*WIN)       // 74 smem cols used
#define SH (TY + 2*WIN)       // 18 smem rows
#define SWP 76                // padded pitch

#define GX 4                  // ceil(246/64)
#define GY 31                 // ceil(246/8)
#define NBLOCKS (GX*GY*BATCH) // 1984

__device__ float g_block_sums[NBLOCKS];

__global__ __launch_bounds__(BDX*BDY)
void contrast_loss_kernel(const float* __restrict__ orig,
                          const float* __restrict__ simu)
{
    __shared__ float sm[6][SH][SWP];

    const int bx = blockIdx.x * TX;
    const int by = blockIdx.y * TY;
    const int b  = blockIdx.z;

    const float* base_o = orig + (size_t)b * NCH * HDIM * HDIM;
    const float* base_s = simu + (size_t)b * NCH * HDIM * HDIM;

    const int tid = threadIdx.y * BDX + threadIdx.x;

    // Cooperative load of 6 planes (3 orig + 3 sim), tile + halo, edge-clamped.
    // For every VALID output pixel all reads are in-bounds; clamped values only
    // feed invalid pixels whose contribution is masked out below.
    #pragma unroll
    for (int plane = 0; plane < 6; ++plane) {
        const float* src = (plane < 3) ? (base_o + plane * HDIM * HDIM)
                                       : (base_s + (plane - 3) * HDIM * HDIM);
        for (int idx = tid; idx < SH * SW; idx += BDX * BDY) {
            int r = idx / SW;
            int c = idx - r * SW;
            int gy = by + r; if (gy > HDIM - 1) gy = HDIM - 1;
            int gx = bx + c; if (gx > HDIM - 1) gx = HDIM - 1;
            sm[plane][r][c] = src[gy * HDIM + gx];
        }
    }
    __syncthreads();

    const int ty = threadIdx.y;            // local output row
    const int lx = threadIdx.x * PX;       // local output col of first pixel
    const int gy_out = by + ty;
    const int gx0 = bx + lx;
    const bool v0 = (gy_out < RDIM) && (gx0     < RDIM);
    const bool v1 = (gy_out < RDIM) && (gx0 + 1 < RDIM);

    // Center pixel values in registers (6 planes x PX pixels).
    float co[NCH][PX], cs[NCH][PX];
    #pragma unroll
    for (int c = 0; c < NCH; ++c) {
        #pragma unroll
        for (int p = 0; p < PX; ++p) {
            co[c][p] = sm[c    ][ty + WIN][lx + WIN + p];
            cs[c][p] = sm[3 + c][ty + WIN][lx + WIN + p];
        }
    }

    float acc0 = 0.f, acc1 = 0.f;

    // Loop over the 11 shift rows. Include (i,j)=(0,0): it contributes
    // exactly zero (center-minus-center), so no branch is needed.
    #pragma unroll 1
    for (int i = 0; i < 11; ++i) {
        const int rr = ty + i;  // smem row for shift i-5

        float dO[PX][11], dS[PX][11];
        #pragma unroll
        for (int j = 0; j < 11; ++j) {
            #pragma unroll
            for (int p = 0; p < PX; ++p) { dO[p][j] = 0.f; dS[p][j] = 0.f; }
        }

        #pragma unroll
        for (int c = 0; c < NCH; ++c) {
            // Register window: columns [lx, lx + PX + 10) of this shift row.
            float wo[PX + 10], ws[PX + 10];
            #pragma unroll
            for (int k = 0; k < PX + 10; ++k) {
                wo[k] = sm[c    ][rr][lx + k];
                ws[k] = sm[3 + c][rr][lx + k];
            }
            #pragma unroll
            for (int j = 0; j < 11; ++j) {
                #pragma unroll
                for (int p = 0; p < PX; ++p) {
                    dO[p][j] += fabsf(co[c][p] - wo[p + j]);
                    dS[p][j] += fabsf(cs[c][p] - ws[p + j]);
                }
            }
        }

        #pragma unroll
        for (int j = 0; j < 11; ++j) {
            acc0 += fabsf(dO[0][j] - dS[0][j]);
            acc1 += fabsf(dO[1][j] - dS[1][j]);
        }
    }

    float acc = (v0 ? acc0 : 0.f) + (v1 ? acc1 : 0.f);

    // Block reduction: warp shuffle, then cross-warp via smem.
    #pragma unroll
    for (int off = 16; off > 0; off >>= 1)
        acc += __shfl_down_sync(0xFFFFFFFFu, acc, off);

    __shared__ float red[BDX * BDY / 32];
    const int warp = tid >> 5;
    const int lane = tid & 31;
    if (lane == 0) red[warp] = acc;
    __syncthreads();

    if (tid == 0) {
        float tot = 0.f;
        #pragma unroll
        for (int wI = 0; wI < BDX * BDY / 32; ++wI) tot += red[wI];
        int bidx = (blockIdx.z * gridDim.y + blockIdx.y) * gridDim.x + blockIdx.x;
        g_block_sums[bidx] = tot;
    }
}

__global__ void reduce_kernel(float* __restrict__ out)
{
    __shared__ double sred[256];
    double s = 0.0;
    for (int i = threadIdx.x; i < NBLOCKS; i += 256)
        s += (double)g_block_sums[i];
    sred[threadIdx.x] = s;
    __syncthreads();
    #pragma unroll
    for (int st = 128; st > 0; st >>= 1) {
        if (threadIdx.x < st) sred[threadIdx.x] += sred[threadIdx.x + st];
        __syncthreads();
    }
    if (threadIdx.x == 0) {
        // count = B * 246 * 246 * 120 = 116190720
        out[0] = (float)(sred[0] / 116190720.0);
    }
}

extern "C" void kernel_launch(void* const* d_in, const int* in_sizes, int n_in,
                              void* d_out, int out_size)
{
    const float* orig = (const float*)d_in[0];
    const float* simu = (const float*)d_in[1];
    // d_in[2] = window_size (5) — shapes are compile-time constants here.
    float* out = (float*)d_out;

    dim3 grid(GX, GY, BATCH);
    dim3 block(BDX, BDY);
    contrast_loss_kernel<<<grid, block>>>(orig, simu);
    reduce_kernel<<<1, 256>>>(out);
}

// round 4
// speedup vs baseline: 1.1300x; 1.1300x over previous
#include <cuda_runtime.h>

// ContrastSSIMLoss: mean over |contrast(orig) - contrast(sim)|
// contrast(img)[b,y,x,s] = sum_c |img[b,c,y+w,x+w] - img[b,c,y+w+i,x+w+j]|
// (i,j) in [-5,5]^2 \ {(0,0)} -> 120 maps; region 246x246; B=16, C=3, H=256, w=5.
//
// Strategy: pack (orig, sim) into one f32x2 lane (add.rn.f32x2 on fma pipe,
// abs via and.b64 on alu pipe). Smem holds interleaved (o,s) float2 cells so
// every packed operand is an aligned 8B value; windows load via LDS.128.
// The (0,0) shift contributes exactly 0, so the shift loops stay uniform 11x11.
// Final mean fused via atomic-ticket last-block reduction (double precision).

#define HDIM 256
#define WIN  5
#define RDIM 246
#define BATCH 16
#define NCH 3

#define TX 64                 // output pixels per block in x
#define TY 8                  // output rows per block
#define BDX 32
#define BDY 8
#define SW 74                 // used cells per row (TX + 2*WIN)
#define SH 18                 // rows (TY + 2*WIN)
#define SWP 76                // padded pitch (cells), keeps 16B alignment

#define GX 4
#define GY 31
#define NBLOCKS (GX*GY*BATCH) // 1984

typedef unsigned long long ull;

#define ABS2_MASK 0x7FFFFFFF7FFFFFFFULL
#define NEG2_MASK 0x8000000080000000ULL

__device__ float g_partial[NBLOCKS];
__device__ unsigned int g_ticket;   // zero-init at load; reset by last block

__device__ __forceinline__ ull add2(ull a, ull b) {
    ull r;
    asm("add.rn.f32x2 %0, %1, %2;" : "=l"(r) : "l"(a), "l"(b));
    return r;
}

__global__ __launch_bounds__(BDX*BDY)
void contrast_loss_kernel(const float* __restrict__ orig,
                          const float* __restrict__ simu,
                          float* __restrict__ out)
{
    __shared__ __align__(16) ull sm[NCH][SH][SWP];

    const int bx = blockIdx.x * TX;
    const int by = blockIdx.y * TY;
    const int b  = blockIdx.z;
    const int tid = threadIdx.y * BDX + threadIdx.x;

    const float* bo = orig + (size_t)b * NCH * HDIM * HDIM;
    const float* bs = simu + (size_t)b * NCH * HDIM * HDIM;

    // Cooperative load: interleave (orig, sim) per cell, edge-clamped.
    // Clamped values only ever feed invalid (masked-out) output pixels.
    #pragma unroll
    for (int ch = 0; ch < NCH; ++ch) {
        const float* po = bo + ch * HDIM * HDIM;
        const float* ps = bs + ch * HDIM * HDIM;
        for (int idx = tid; idx < SH * SW; idx += BDX * BDY) {
            int r = idx / SW;
            int c = idx - r * SW;
            int gy = by + r; if (gy > HDIM - 1) gy = HDIM - 1;
            int gx = bx + c; if (gx > HDIM - 1) gx = HDIM - 1;
            float2* cell = (float2*)&sm[ch][r][c];
            *cell = make_float2(po[gy * HDIM + gx], ps[gy * HDIM + gx]);
        }
    }
    __syncthreads();

    const int ty = threadIdx.y;
    const int lx = threadIdx.x * 2;        // first of 2 adjacent pixels (cells)
    const int gy_out = by + ty;
    const int gx0 = bx + lx;
    const bool vld0 = (gy_out < RDIM) && (gx0     < RDIM);
    const bool vld1 = (gy_out < RDIM) && (gx0 + 1 < RDIM);

    // Negated packed centers: diff = w + (-c); |c-w| == |w-c|.
    ull nc[NCH][2];
    #pragma unroll
    for (int ch = 0; ch < NCH; ++ch) {
        #pragma unroll
        for (int p = 0; p < 2; ++p)
            nc[ch][p] = sm[ch][ty + WIN][lx + WIN + p] ^ NEG2_MASK;
    }

    float acc0 = 0.f, acc1 = 0.f;

    #pragma unroll 1
    for (int i = 0; i < 11; ++i) {
        const int rr = ty + i;
        ull d[2][11];   // packed (dO, dS) accumulators per (pixel, j)

        #pragma unroll
        for (int ch = 0; ch < NCH; ++ch) {
            // 12-cell window via 6x LDS.128 (16B-aligned: lx even).
            ull w[12];
            const ulonglong2* rowp = (const ulonglong2*)&sm[ch][rr][lx];
            #pragma unroll
            for (int q = 0; q < 6; ++q) {
                ulonglong2 t = rowp[q];
                w[2*q]   = t.x;
                w[2*q+1] = t.y;
            }
            #pragma unroll
            for (int j = 0; j < 11; ++j) {
                #pragma unroll
                for (int p = 0; p < 2; ++p) {
                    ull df = add2(w[j + p], nc[ch][p]) & ABS2_MASK;
                    d[p][j] = (ch == 0) ? df : add2(d[p][j], df);
                }
            }
        }

        #pragma unroll
        for (int j = 0; j < 11; ++j) {
            float lo0, hi0, lo1, hi1;
            asm("mov.b64 {%0,%1}, %2;" : "=f"(lo0), "=f"(hi0) : "l"(d[0][j]));
            asm("mov.b64 {%0,%1}, %2;" : "=f"(lo1), "=f"(hi1) : "l"(d[1][j]));
            acc0 += fabsf(lo0 - hi0);
            acc1 += fabsf(lo1 - hi1);
        }
    }

    float acc = (vld0 ? acc0 : 0.f) + (vld1 ? acc1 : 0.f);

    // Block reduction.
    #pragma unroll
    for (int off = 16; off > 0; off >>= 1)
        acc += __shfl_down_sync(0xFFFFFFFFu, acc, off);

    __shared__ float red[BDX * BDY / 32];
    const int warp = tid >> 5;
    const int lane = tid & 31;
    if (lane == 0) red[warp] = acc;
    __syncthreads();

    __shared__ bool is_last;
    if (tid == 0) {
        float tot = 0.f;
        #pragma unroll
        for (int wI = 0; wI < BDX * BDY / 32; ++wI) tot += red[wI];
        int bidx = (blockIdx.z * gridDim.y + blockIdx.y) * gridDim.x + blockIdx.x;
        g_partial[bidx] = tot;
        __threadfence();
        unsigned t = atomicAdd(&g_ticket, 1u);
        is_last = (t == NBLOCKS - 1);
    }
    __syncthreads();

    if (is_last) {
        // Deterministic final reduce (fixed order), double precision.
        double s = 0.0;
        for (int i2 = tid; i2 < NBLOCKS; i2 += BDX * BDY)
            s += (double)g_partial[i2];

        double* dred = (double*)&sm[0][0][0];   // reuse smem (sized far larger)
        dred[tid] = s;
        __syncthreads();
        #pragma unroll
        for (int st = 128; st > 0; st >>= 1) {
            if (tid < st) dred[tid] += dred[tid + st];
            __syncthreads();
        }
        if (tid == 0) {
            // count = B * 246 * 246 * 120 = 116190720
            out[0] = (float)(dred[0] / 116190720.0);
            g_ticket = 0;   // reset for next (graph-replayed) launch
        }
    }
}

extern "C" void kernel_launch(void* const* d_in, const int* in_sizes, int n_in,
                              void* d_out, int out_size)
{
    const float* orig = (const float*)d_in[0];
    const float* simu = (const float*)d_in[1];
    // d_in[2] = window_size (5): compile-time constant here.
    float* out = (float*)d_out;

    dim3 grid(GX, GY, BATCH);
    dim3 block(BDX, BDY);
    contrast_loss_kernel<<<grid, block>>>(orig, simu, out);
}

// round 16
// speedup vs baseline: 1.7004x; 1.5048x over previous
#include <cuda_runtime.h>

// ContrastSSIMLoss: mean over |contrast(orig) - contrast(sim)|
// contrast(img)[b,y,x,s] = sum_c |img[b,c,y+w,x+w] - img[b,c,y+w+i,x+w+j]|
// (i,j) in [-5,5]^2 \ {(0,0)} -> 120 maps; region 246x246; B=16, C=3, H=256, w=5.
//
// Exploit e(p,s) == e(p+s,-s) (bitwise-exact per term). Compute only the
// 60 half-space shifts (si in [-5,-1], all sj; si=0, sj in [-5,-1]) and
// count each term twice:
//   accP += e              (pixel-p contribution; masked by p-validity)
//   accQ += py*pw[j+p]*e   (partner q=p+s contribution, 0/1 weights)
// Host grid spans x in [-5,250], y in [0,255] so EVERY partner host exists
// (p = q - s needs p_col >= -5 when sj > 0 and q_col < sj).
// (orig,sim) packed in one f32x2 lane: add.rn.f32x2 on fma pipe, abs via
// 64-bit AND on alu pipe, windows via LDS.128 from interleaved smem.

#define HDIM 256
#define WIN  5
#define RDIM 246
#define BATCH 16
#define NCH 3

#define TX 64
#define TY 8
#define BDX 32
#define BDY 8
#define SW 74                 // used cells per row (TX + 2*WIN)
#define SH 13                 // rows: ty + i, ty<=7, i<=5 -> max 12
#define SWP 76                // padded pitch (cells); row = 608B, 16B-aligned

#define GX 4                  // x hosts: -5 .. 250  (4*64 = 256 cols)
#define GY 32                 // y hosts:  0 .. 255
#define NBLOCKS (GX*GY*BATCH) // 2048

typedef unsigned long long ull;

#define ABS2_MASK 0x7FFFFFFF7FFFFFFFULL
#define NEG2_MASK 0x8000000080000000ULL

__device__ float g_partial[NBLOCKS];
__device__ unsigned int g_ticket;   // zero-init; reset by last block each run

__device__ __forceinline__ ull add2(ull a, ull b) {
    ull r;
    asm("add.rn.f32x2 %0, %1, %2;" : "=l"(r) : "l"(a), "l"(b));
    return r;
}

__global__ __launch_bounds__(BDX*BDY)
void contrast_loss_kernel(const float* __restrict__ orig,
                          const float* __restrict__ simu,
                          float* __restrict__ out)
{
    __shared__ __align__(16) ull sm[NCH][SH][SWP];

    const int bx = blockIdx.x * TX - WIN;   // host columns start at -5
    const int by = blockIdx.y * TY;
    const int b  = blockIdx.z;
    const int tid = threadIdx.y * BDX + threadIdx.x;

    const float* bo = orig + (size_t)b * NCH * HDIM * HDIM;
    const float* bs = simu + (size_t)b * NCH * HDIM * HDIM;

    // Cooperative load: interleaved (orig, sim) cells, edge-clamped both ends.
    // Clamped values only ever feed weight-0 / masked-out contributions.
    #pragma unroll
    for (int ch = 0; ch < NCH; ++ch) {
        const float* po = bo + ch * HDIM * HDIM;
        const float* ps = bs + ch * HDIM * HDIM;
        for (int idx = tid; idx < SH * SW; idx += BDX * BDY) {
            int r = idx / SW;
            int c = idx - r * SW;
            int gy = by + r; if (gy > HDIM - 1) gy = HDIM - 1;
            int gx = bx + c;
            if (gx < 0) gx = 0;
            if (gx > HDIM - 1) gx = HDIM - 1;
            float2* cell = (float2*)&sm[ch][r][c];
            *cell = make_float2(po[gy * HDIM + gx], ps[gy * HDIM + gx]);
        }
    }
    __syncthreads();

    const int ty = threadIdx.y;
    const int lx = threadIdx.x * 2;        // first of 2 adjacent host pixels
    const int gy_out = by + ty;
    const int gx0 = bx + lx;               // may be negative (host-only)
    const bool vld0 = (gy_out < RDIM) && (gx0     >= 0) && (gx0     < RDIM);
    const bool vld1 = (gy_out < RDIM) && (gx0 + 1 >= 0) && (gx0 + 1 < RDIM);

    // Partner-x validity weights: window cell k holds pixel x = gx0 + k - 5.
    float pw[12];
    #pragma unroll
    for (int k = 0; k < 12; ++k) {
        int pxx = gx0 + k - WIN;
        pw[k] = (pxx >= 0 && pxx < RDIM) ? 1.f : 0.f;
    }

    // Negated packed centers (center = smem row ty+5, col lx+5+p).
    ull nc[NCH][2];
    #pragma unroll
    for (int ch = 0; ch < NCH; ++ch) {
        #pragma unroll
        for (int p = 0; p < 2; ++p)
            nc[ch][p] = sm[ch][ty + WIN][lx + WIN + p] ^ NEG2_MASK;
    }

    float accP0 = 0.f, accP1 = 0.f, accQ = 0.f;

    // ----- si in [-5,-1]: full j range (11 shifts per row) -----
    #pragma unroll 1
    for (int i = 0; i < 5; ++i) {
        const int rr = ty + i;
        const int prow = gy_out + i - WIN;   // partner y (= gy_out + si)
        const float py = (prow >= 0 && prow < RDIM) ? 1.f : 0.f;

        ull d[2][11];
        #pragma unroll
        for (int ch = 0; ch < NCH; ++ch) {
            ull w[12];
            const ulonglong2* rowp = (const ulonglong2*)&sm[ch][rr][lx];
            #pragma unroll
            for (int q = 0; q < 6; ++q) {
                ulonglong2 t = rowp[q];
                w[2*q]   = t.x;
                w[2*q+1] = t.y;
            }
            #pragma unroll
            for (int j = 0; j < 11; ++j) {
                #pragma unroll
                for (int p = 0; p < 2; ++p) {
                    ull df = add2(w[j + p], nc[ch][p]) & ABS2_MASK;
                    d[p][j] = (ch == 0) ? df : add2(d[p][j], df);
                }
            }
        }

        float Qi = 0.f;
        #pragma unroll
        for (int j = 0; j < 11; ++j) {
            float lo0, hi0, lo1, hi1;
            asm("mov.b64 {%0,%1}, %2;" : "=f"(lo0), "=f"(hi0) : "l"(d[0][j]));
            asm("mov.b64 {%0,%1}, %2;" : "=f"(lo1), "=f"(hi1) : "l"(d[1][j]));
            float e0 = fabsf(lo0 - hi0);
            float e1 = fabsf(lo1 - hi1);
            accP0 += e0;
            accP1 += e1;
            Qi = fmaf(e0, pw[j],     Qi);
            Qi = fmaf(e1, pw[j + 1], Qi);
        }
        accQ = fmaf(py, Qi, accQ);
    }

    // ----- si = 0: sj in [-5,-1] only (5 shifts) -----
    {
        const int rr = ty + WIN;
        const float py = (gy_out < RDIM) ? 1.f : 0.f;

        ull d[2][5];
        #pragma unroll
        for (int ch = 0; ch < NCH; ++ch) {
            ull w[6];
            const ulonglong2* rowp = (const ulonglong2*)&sm[ch][rr][lx];
            #pragma unroll
            for (int q = 0; q < 3; ++q) {
                ulonglong2 t = rowp[q];
                w[2*q]   = t.x;
                w[2*q+1] = t.y;
            }
            #pragma unroll
            for (int j = 0; j < 5; ++j) {
                #pragma unroll
                for (int p = 0; p < 2; ++p) {
                    ull df = add2(w[j + p], nc[ch][p]) & ABS2_MASK;
                    d[p][j] = (ch == 0) ? df : add2(d[p][j], df);
                }
            }
        }

        float Qi = 0.f;
        #pragma unroll
        for (int j = 0; j < 5; ++j) {
            float lo0, hi0, lo1, hi1;
            asm("mov.b64 {%0,%1}, %2;" : "=f"(lo0), "=f"(hi0) : "l"(d[0][j]));
            asm("mov.b64 {%0,%1}, %2;" : "=f"(lo1), "=f"(hi1) : "l"(d[1][j]));
            float e0 = fabsf(lo0 - hi0);
            float e1 = fabsf(lo1 - hi1);
            accP0 += e0;
            accP1 += e1;
            Qi = fmaf(e0, pw[j],     Qi);
            Qi = fmaf(e1, pw[j + 1], Qi);
        }
        accQ = fmaf(py, Qi, accQ);
    }

    float acc = (vld0 ? accP0 : 0.f) + (vld1 ? accP1 : 0.f) + accQ;

    // Block reduction.
    #pragma unroll
    for (int off = 16; off > 0; off >>= 1)
        acc += __shfl_down_sync(0xFFFFFFFFu, acc, off);

    __shared__ float red[BDX * BDY / 32];
    const int warp = tid >> 5;
    const int lane = tid & 31;
    if (lane == 0) red[warp] = acc;
    __syncthreads();

    __shared__ bool is_last;
    if (tid == 0) {
        float tot = 0.f;
        #pragma unroll
        for (int wI = 0; wI < BDX * BDY / 32; ++wI) tot += red[wI];
        int bidx = (blockIdx.z * gridDim.y + blockIdx.y) * gridDim.x + blockIdx.x;
        g_partial[bidx] = tot;
        __threadfence();
        unsigned t = atomicAdd(&g_ticket, 1u);
        is_last = (t == NBLOCKS - 1);
    }
    __syncthreads();

    if (is_last) {
        // Deterministic final reduce (fixed order), double precision.
        double s = 0.0;
        for (int i2 = tid; i2 < NBLOCKS; i2 += BDX * BDY)
            s += (double)g_partial[i2];

        double* dred = (double*)&sm[0][0][0];   // reuse smem
        dred[tid] = s;
        __syncthreads();
        #pragma unroll
        for (int st = 128; st > 0; st >>= 1) {
            if (tid < st) dred[tid] += dred[tid + st];
            __syncthreads();
        }
        if (tid == 0) {
            // count = B * 246 * 246 * 120 = 116190720
            out[0] = (float)(dred[0] / 116190720.0);
            g_ticket = 0;   // reset for graph replay
        }
    }
}

extern "C" void kernel_launch(void* const* d_in, const int* in_sizes, int n_in,
                              void* d_out, int out_size)
{
    const float* orig = (const float*)d_in[0];
    const float* simu = (const float*)d_in[1];
    // d_in[2] = window_size (5): compile-time constant here.
    float* out = (float*)d_out;

    dim3 grid(GX, GY, BATCH);
    dim3 block(BDX, BDY);
    contrast_loss_kernel<<<grid, block>>>(orig, simu, out);
}